// round 1
// baseline (speedup 1.0000x reference)
#include <cuda_runtime.h>
#include <math.h>

// Problem constants
#define T_LEN   16
#define C_DIM   192
#define DIN     384
#define DSTATE  16
#define DTRANK  12
#define XP_OUT  44      // DTRANK + 2*DSTATE
#define HW      784     // 28*28
#define STRIDE  388     // padded row stride for 384-wide smem arrays (bank-conflict-friendly)

__device__ __forceinline__ float siluf(float v) {
    // v / (1 + e^-v), fast path
    return __fdividef(v, 1.0f + __expf(-v));
}

__global__ __launch_bounds__(256, 1)
void mamba_fused_kernel(const float* __restrict__ x,
                        const float* __restrict__ norm_w,
                        const float* __restrict__ in_proj_w,   // (192, 768)
                        const float* __restrict__ conv_w,      // (384, 4)
                        const float* __restrict__ conv_b,      // (384,)
                        const float* __restrict__ x_proj_w,    // (384, 44)
                        const float* __restrict__ dt_proj_w,   // (12, 384)
                        const float* __restrict__ dt_proj_b,   // (384,)
                        const float* __restrict__ A_log,       // (384, 16)
                        const float* __restrict__ Dp,          // (384,)
                        const float* __restrict__ out_proj_w,  // (384, 192)
                        float* __restrict__ out)
{
    extern __shared__ float sm[];
    float* s_xn = sm;                    // 16*192  = 3072
    float* s_u  = s_xn + 16 * C_DIM;     // 16*388  = 6208  (aliased as s_y later)
    float* s_z  = s_u  + 16 * STRIDE;    // 6208  (holds silu(z))
    float* s_uc = s_z  + 16 * STRIDE;    // 6208
    float* s_dt = s_uc + 16 * STRIDE;    // 6208
    float* s_db = s_dt + 16 * STRIDE;    // 16*44 = 704  (dt_raw | B | C)
    float* s_y  = s_u;                   // alias: u dead after conv

    const int tid  = threadIdx.x;
    const int lane = tid & 31;
    const int wid  = tid >> 5;

    const int n  = blockIdx.x;
    const int b  = n / HW;
    const int hw = n - b * HW;
    const size_t tstride = (size_t)HW * C_DIM;
    const size_t base0   = ((size_t)b * T_LEN * HW + hw) * C_DIM;  // index of (t=0, c=0)

    // ---------------- Phase A: load + RMSNorm -> s_xn ----------------
    for (int t = wid; t < T_LEN; t += 8) {
        const float* row = x + base0 + (size_t)t * tstride;
        float v[6];
        float ss = 0.f;
        #pragma unroll
        for (int i = 0; i < 6; i++) { v[i] = row[lane + 32 * i]; ss = fmaf(v[i], v[i], ss); }
        #pragma unroll
        for (int o = 16; o; o >>= 1) ss += __shfl_xor_sync(0xffffffffu, ss, o);
        float nrm = rsqrtf(ss * (1.0f / 192.0f) + 1e-6f);
        #pragma unroll
        for (int i = 0; i < 6; i++)
            s_xn[t * C_DIM + lane + 32 * i] = v[i] * nrm * norm_w[lane + 32 * i];
    }
    __syncthreads();

    // ---------------- Phase B: in_proj (16x192 @ 192x768) -> u, silu(z) ----------------
    {
        float acc0[16], acc1[16], acc2[16];
        #pragma unroll
        for (int t = 0; t < 16; t++) { acc0[t] = 0.f; acc1[t] = 0.f; acc2[t] = 0.f; }
        for (int k = 0; k < C_DIM; k++) {
            const float* wr = in_proj_w + k * 768;
            float w0 = wr[tid];
            float w1 = wr[tid + 256];
            float w2 = wr[tid + 512];
            #pragma unroll
            for (int t = 0; t < 16; t++) {
                float xv = s_xn[t * C_DIM + k];
                acc0[t] = fmaf(xv, w0, acc0[t]);
                acc1[t] = fmaf(xv, w1, acc1[t]);
                acc2[t] = fmaf(xv, w2, acc2[t]);
            }
        }
        // col0 = tid (<384 -> u), col1 = tid+256, col2 = tid+512 (>=384 -> z)
        #pragma unroll
        for (int t = 0; t < 16; t++) {
            s_u[t * STRIDE + tid] = acc0[t];
            if (tid < 128) s_u[t * STRIDE + tid + 256] = acc1[t];
            else           s_z[t * STRIDE + tid - 128] = siluf(acc1[t]);
            s_z[t * STRIDE + tid + 128] = siluf(acc2[t]);
        }
    }
    __syncthreads();

    // ---------------- Phase C: causal depthwise conv + silu -> s_uc ----------------
    for (int idx = tid; idx < T_LEN * DIN; idx += 256) {
        int t = idx / DIN;
        int c = idx - t * DIN;
        float acc = conv_b[c];
        const float* cw = conv_w + c * 4;
        #pragma unroll
        for (int j = 0; j < 4; j++) {
            int ts = t - 3 + j;
            if (ts >= 0) acc = fmaf(s_u[ts * STRIDE + c], cw[j], acc);
        }
        s_uc[t * STRIDE + c] = siluf(acc);
    }
    __syncthreads();

    // ---------------- Phase D: x_proj (16x384 @ 384x44) -> s_db ----------------
    for (int o = tid; o < T_LEN * XP_OUT; o += 256) {
        int j = o >> 4;        // output column 0..43
        int t = o & 15;
        float acc = 0.f;
        const float* ucr = s_uc + t * STRIDE;
        for (int k = 0; k < DIN; k++)
            acc = fmaf(ucr[k], x_proj_w[k * XP_OUT + j], acc);
        s_db[t * XP_OUT + j] = acc;
    }
    __syncthreads();

    // ---------------- Phase E: dt_proj + softplus -> s_dt ----------------
    for (int o = tid; o < T_LEN * DIN; o += 256) {
        int t = o / DIN;
        int c = o - t * DIN;
        float acc = dt_proj_b[c];
        const float* dr = s_db + t * XP_OUT;
        #pragma unroll
        for (int r = 0; r < DTRANK; r++)
            acc = fmaf(dr[r], dt_proj_w[r * DIN + c], acc);
        float sp = (acc > 20.f) ? acc : log1pf(__expf(acc));
        s_dt[t * STRIDE + c] = sp;
    }
    __syncthreads();

    // ---------------- Phase F: selective scan -> s_y (aliases s_u) ----------------
    for (int c = tid; c < DIN; c += 256) {
        float Areg[DSTATE];
        #pragma unroll
        for (int s = 0; s < DSTATE; s++)
            Areg[s] = -__expf(A_log[c * DSTATE + s]);
        float h[DSTATE];
        #pragma unroll
        for (int s = 0; s < DSTATE; s++) h[s] = 0.f;
        float Dc = Dp[c];

        for (int t = 0; t < T_LEN; t++) {
            float dtv = s_dt[t * STRIDE + c];
            float ucv = s_uc[t * STRIDE + c];
            float du  = dtv * ucv;
            const float* Bm = s_db + t * XP_OUT + DTRANK;
            const float* Cm = Bm + DSTATE;
            float y = 0.f;
            #pragma unroll
            for (int s = 0; s < DSTATE; s++) {
                float dA = __expf(dtv * Areg[s]);
                float hb = fmaf(h[s], dA, du * Bm[s]);
                h[s] = hb;
                y = fmaf(hb, Cm[s], y);
            }
            y = fmaf(ucv, Dc, y);
            s_y[t * STRIDE + c] = y * s_z[t * STRIDE + c];
        }
    }
    __syncthreads();

    // ---------------- Phase G: out_proj (16x384 @ 384x192) + residual -> out ----------------
    if (tid < C_DIM) {
        const int c = tid;
        float acc[16];
        #pragma unroll
        for (int t = 0; t < 16; t++) acc[t] = 0.f;
        for (int k = 0; k < DIN; k++) {
            float w = out_proj_w[k * C_DIM + c];
            #pragma unroll
            for (int t = 0; t < 16; t++)
                acc[t] = fmaf(s_y[t * STRIDE + k], w, acc[t]);
        }
        #pragma unroll
        for (int t = 0; t < 16; t++) {
            size_t gi = base0 + (size_t)t * tstride + c;
            out[gi] = x[gi] + acc[t];
        }
    }
}

extern "C" void kernel_launch(void* const* d_in, const int* in_sizes, int n_in,
                              void* d_out, int out_size)
{
    (void)in_sizes; (void)n_in; (void)out_size;
    const float* x         = (const float*)d_in[0];
    const float* norm_w    = (const float*)d_in[1];
    const float* in_proj_w = (const float*)d_in[2];
    const float* conv_w    = (const float*)d_in[3];
    const float* conv_b    = (const float*)d_in[4];
    const float* x_proj_w  = (const float*)d_in[5];
    const float* dt_proj_w = (const float*)d_in[6];
    const float* dt_proj_b = (const float*)d_in[7];
    const float* A_log     = (const float*)d_in[8];
    const float* Dp        = (const float*)d_in[9];
    const float* out_pw    = (const float*)d_in[10];
    float* out = (float*)d_out;

    const int smem_bytes = (16 * 192 + 4 * 16 * 388 + 16 * 44) * (int)sizeof(float); // 114432
    cudaFuncSetAttribute(mamba_fused_kernel,
                         cudaFuncAttributeMaxDynamicSharedMemorySize, smem_bytes);

    dim3 grid(2 * HW);   // B * H * W = 1568 sequences
    dim3 block(256);
    mamba_fused_kernel<<<grid, block, smem_bytes>>>(
        x, norm_w, in_proj_w, conv_w, conv_b, x_proj_w,
        dt_proj_w, dt_proj_b, A_log, Dp, out_pw, out);
}